// round 1
// baseline (speedup 1.0000x reference)
#include <cuda_runtime.h>
#include <cuda_bf16.h>
#include <cstdint>

// Problem constants (fixed shapes for this problem instance)
#define BB   32      // batch
#define DD   4096    // model dim
#define HH   32      // q heads
#define HKV  8       // kv heads
#define GG   4       // q heads per kv head
#define DH   128     // head dim
#define TT   4096    // cache length
#define EQKV 6144    // 4096 + 1024 + 1024
#define CHUNK 128    // attention t-chunk per block
#define NCHUNK 32    // TT / CHUNK
#define SPLITS 32    // K-splits for projections
#define DSPL 128     // d per split (4096/32)

// ---------------- scratch (device globals; no runtime allocation) ----------------
__device__ float g_xq[BB * HH * DH];
__device__ float g_xk[BB * HKV * DH];
__device__ float g_v [BB * HKV * DH];
__device__ float g_q [BB * HH * DH];
__device__ float g_k [BB * HKV * DH];
__device__ float g_attn[BB * HH * DH];
__device__ float g_P1[SPLITS * BB * EQKV];          // qkv partials
__device__ float g_P2[SPLITS * BB * DD];            // wo partials
__device__ float g_pacc[BB * HKV * NCHUNK * GG * DH];  // flash partial acc
__device__ float g_pml [BB * HKV * NCHUNK * GG * 2];   // flash partial (m,l)

// ---------------- packed fp32x2 helpers (FFMA2 path, sm_100+) ----------------
__device__ __forceinline__ unsigned long long pk2(float lo, float hi) {
    unsigned long long r;
    asm("mov.b64 %0, {%1,%2};" : "=l"(r) : "f"(lo), "f"(hi));
    return r;
}
__device__ __forceinline__ void upk2(unsigned long long v, float& lo, float& hi) {
    asm("mov.b64 {%0,%1}, %2;" : "=f"(lo), "=f"(hi) : "l"(v));
}
__device__ __forceinline__ void fma2(unsigned long long& d, unsigned long long a, unsigned long long b) {
    asm("fma.rn.f32x2 %0, %1, %2, %0;" : "+l"(d) : "l"(a), "l"(b));
}

// ---------------- projection GEMV body ----------------
// out[b][e] = sum_d x[b][d] * w[d][e], M=32 rows, split over d.
// Block: 256 threads, 512 columns (thread owns cols tid and tid+256), 128 d rows.
// Batch rows packed in pairs -> 2 fp32 MACs per FFMA2 instruction.
__device__ __forceinline__ void proj_body(
    const float* __restrict__ x, const float* __restrict__ w,
    int Ew, int le0, int gcol0, int d0,
    float* __restrict__ part, int partE)
{
    __shared__ float xs[DSPL * BB];   // 16 KB, x tile packed [d_local][b]
    const int tid = threadIdx.x;

    #pragma unroll
    for (int k = 0; k < 16; k++) {
        int idx = tid + k * 256;
        int dl = idx >> 5, b = idx & 31;
        xs[dl * 32 + b] = x[b * DD + d0 + dl];
    }
    __syncthreads();

    const unsigned long long* xs2 = (const unsigned long long*)xs; // [d_local][16 b-pairs]

    unsigned long long accA[16], accB[16];
    #pragma unroll
    for (int j = 0; j < 16; j++) { accA[j] = 0ull; accB[j] = 0ull; }

    const int colA = le0 + tid;
    const int colB = colA + 256;
    const float* wp = w + (size_t)d0 * Ew;

    #pragma unroll 2
    for (int dl = 0; dl < DSPL; dl++) {
        float wa = wp[colA];
        float wb = wp[colB];
        unsigned long long wa2 = pk2(wa, wa);
        unsigned long long wb2 = pk2(wb, wb);
        const unsigned long long* xr = xs2 + dl * 16;
        #pragma unroll
        for (int j = 0; j < 16; j++) {
            unsigned long long xj = xr[j];
            fma2(accA[j], wa2, xj);
            fma2(accB[j], wb2, xj);
        }
        wp += Ew;
    }

    const int split = blockIdx.y;
    float* pb = part + (size_t)split * BB * partE;
    #pragma unroll
    for (int j = 0; j < 16; j++) {
        float lo, hi;
        upk2(accA[j], lo, hi);
        pb[(size_t)(2 * j) * partE + gcol0 + tid] = lo;
        pb[(size_t)(2 * j + 1) * partE + gcol0 + tid] = hi;
        upk2(accB[j], lo, hi);
        pb[(size_t)(2 * j) * partE + gcol0 + 256 + tid] = lo;
        pb[(size_t)(2 * j + 1) * partE + gcol0 + 256 + tid] = hi;
    }
}

__global__ void __launch_bounds__(256)
proj_qkv_kernel(const float* __restrict__ x, const float* __restrict__ wq,
                const float* __restrict__ wk, const float* __restrict__ wv)
{
    int e0 = blockIdx.x * 512;
    const float* w; int Ew, le0;
    if (e0 < 4096)      { w = wq; Ew = 4096; le0 = e0; }
    else if (e0 < 5120) { w = wk; Ew = 1024; le0 = e0 - 4096; }
    else                { w = wv; Ew = 1024; le0 = e0 - 5120; }
    proj_body(x, w, Ew, le0, e0, blockIdx.y * DSPL, g_P1, EQKV);
}

__global__ void __launch_bounds__(256)
proj_o_kernel(const float* __restrict__ wo)
{
    int e0 = blockIdx.x * 512;
    proj_body(g_attn, wo, DD, e0, e0, blockIdx.y * DSPL, g_P2, DD);
}

// ---------------- reductions over K-splits ----------------
__global__ void reduce_qkv_kernel()
{
    int idx = blockIdx.x * 256 + threadIdx.x;
    if (idx >= BB * EQKV) return;
    int b = idx / EQKV, col = idx % EQKV;
    float s = 0.f;
    #pragma unroll 8
    for (int sp = 0; sp < SPLITS; sp++)
        s += g_P1[((size_t)sp * BB + b) * EQKV + col];
    if (col < 4096)      g_xq[b * 4096 + col] = s;
    else if (col < 5120) g_xk[b * 1024 + (col - 4096)] = s;
    else                 g_v [b * 1024 + (col - 5120)] = s;
}

__global__ void reduce_o_kernel(float* __restrict__ out)
{
    int idx = blockIdx.x * 256 + threadIdx.x;
    if (idx >= BB * DD) return;
    int b = idx >> 12, col = idx & 4095;
    float s = 0.f;
    #pragma unroll 8
    for (int sp = 0; sp < SPLITS; sp++)
        s += g_P2[((size_t)sp * BB + b) * DD + col];
    out[b * DD + col] = s;
}

// ---------------- RoPE: q[b,h,e] = sum_d xq[b,h,d] * rot[b,d,e] ----------------
__global__ void rotate_kernel(const float* __restrict__ rot, int rot_b_stride)
{
    int hh = blockIdx.x, b = blockIdx.y, tid = threadIdx.x;
    __shared__ float xs[DH];
    const float* src; float* dst;
    if (hh < HH) { src = g_xq + (b * HH + hh) * DH; dst = g_q + (b * HH + hh) * DH; }
    else         { src = g_xk + (b * HKV + (hh - HH)) * DH; dst = g_k + (b * HKV + (hh - HH)) * DH; }
    xs[tid] = src[tid];
    __syncthreads();
    const float* R = rot + (size_t)b * rot_b_stride;
    float a = 0.f;
    #pragma unroll 8
    for (int d = 0; d < DH; d++) a += xs[d] * R[d * DH + tid];
    dst[tid] = a;
}

// ---------------- flash decode, split-KV ----------------
// grid (NCHUNK, HKV, B), block 256 (8 warps x 16 rows each)
__global__ void __launch_bounds__(256)
attn_kernel(const float* __restrict__ kcache, const float* __restrict__ vcache,
            const int* __restrict__ sp_ptr)
{
    const int chunk = blockIdx.x, kvh = blockIdx.y, b = blockIdx.z;
    const int sp = *sp_ptr;
    const int t0 = chunk * CHUNK;
    if (t0 > sp) return;

    const int wid = threadIdx.x >> 5, lane = threadIdx.x & 31;
    const int bkv = b * HKV + kvh;

    __shared__ float s_s[GG][CHUNK];
    __shared__ float s_acc[8][GG][DH];
    __shared__ float s_red[8][GG];
    __shared__ float s_lred[8][GG];

    const float scale = 0.08838834764831845f;  // 1/sqrt(128)
    float4 q4[GG];
    #pragma unroll
    for (int g = 0; g < GG; g++) {
        float4 t = *(const float4*)(g_q + (size_t)(b * HH + kvh * GG + g) * DH + 4 * lane);
        q4[g] = make_float4(t.x * scale, t.y * scale, t.z * scale, t.w * scale);
    }

    const float* kbase = kcache + (size_t)bkv * TT * DH;
    const float* vbase = vcache + (size_t)bkv * TT * DH;
    const int rbase = wid * 16;

    // ---- score phase ----
    float wm0 = -1e30f, wm1 = -1e30f, wm2 = -1e30f, wm3 = -1e30f;
    #pragma unroll 4
    for (int i = 0; i < 16; i++) {
        int t = t0 + rbase + i;
        float sv0, sv1, sv2, sv3;
        if (t <= sp) {
            const float* kp = (t == sp) ? (g_k + (size_t)bkv * DH)
                                        : (kbase + (size_t)t * DH);
            float4 kv = *(const float4*)(kp + 4 * lane);
            sv0 = q4[0].x*kv.x + q4[0].y*kv.y + q4[0].z*kv.z + q4[0].w*kv.w;
            sv1 = q4[1].x*kv.x + q4[1].y*kv.y + q4[1].z*kv.z + q4[1].w*kv.w;
            sv2 = q4[2].x*kv.x + q4[2].y*kv.y + q4[2].z*kv.z + q4[2].w*kv.w;
            sv3 = q4[3].x*kv.x + q4[3].y*kv.y + q4[3].z*kv.z + q4[3].w*kv.w;
            #pragma unroll
            for (int off = 16; off; off >>= 1) {
                sv0 += __shfl_xor_sync(0xffffffffu, sv0, off);
                sv1 += __shfl_xor_sync(0xffffffffu, sv1, off);
                sv2 += __shfl_xor_sync(0xffffffffu, sv2, off);
                sv3 += __shfl_xor_sync(0xffffffffu, sv3, off);
            }
        } else {
            sv0 = sv1 = sv2 = sv3 = -1e30f;
        }
        if (lane == 0) {
            s_s[0][rbase + i] = sv0; s_s[1][rbase + i] = sv1;
            s_s[2][rbase + i] = sv2; s_s[3][rbase + i] = sv3;
        }
        wm0 = fmaxf(wm0, sv0); wm1 = fmaxf(wm1, sv1);
        wm2 = fmaxf(wm2, sv2); wm3 = fmaxf(wm3, sv3);
    }
    if (lane == 0) { s_red[wid][0] = wm0; s_red[wid][1] = wm1; s_red[wid][2] = wm2; s_red[wid][3] = wm3; }
    __syncthreads();

    float m0 = -1e30f, m1 = -1e30f, m2 = -1e30f, m3 = -1e30f;
    #pragma unroll
    for (int w = 0; w < 8; w++) {
        m0 = fmaxf(m0, s_red[w][0]); m1 = fmaxf(m1, s_red[w][1]);
        m2 = fmaxf(m2, s_red[w][2]); m3 = fmaxf(m3, s_red[w][3]);
    }

    // ---- value phase ----
    float4 a0 = {0,0,0,0}, a1 = {0,0,0,0}, a2 = {0,0,0,0}, a3 = {0,0,0,0};
    float l0 = 0.f, l1 = 0.f, l2 = 0.f, l3 = 0.f;
    #pragma unroll 4
    for (int i = 0; i < 16; i++) {
        int t = t0 + rbase + i;
        if (t > sp) continue;
        const float* vp = (t == sp) ? (g_v + (size_t)bkv * DH)
                                    : (vbase + (size_t)t * DH);
        float4 vv = *(const float4*)(vp + 4 * lane);
        int tl = rbase + i;
        float p0 = __expf(s_s[0][tl] - m0);
        float p1 = __expf(s_s[1][tl] - m1);
        float p2 = __expf(s_s[2][tl] - m2);
        float p3 = __expf(s_s[3][tl] - m3);
        l0 += p0; l1 += p1; l2 += p2; l3 += p3;
        a0.x += p0*vv.x; a0.y += p0*vv.y; a0.z += p0*vv.z; a0.w += p0*vv.w;
        a1.x += p1*vv.x; a1.y += p1*vv.y; a1.z += p1*vv.z; a1.w += p1*vv.w;
        a2.x += p2*vv.x; a2.y += p2*vv.y; a2.z += p2*vv.z; a2.w += p2*vv.w;
        a3.x += p3*vv.x; a3.y += p3*vv.y; a3.z += p3*vv.z; a3.w += p3*vv.w;
    }
    *(float4*)&s_acc[wid][0][4 * lane] = a0;
    *(float4*)&s_acc[wid][1][4 * lane] = a1;
    *(float4*)&s_acc[wid][2][4 * lane] = a2;
    *(float4*)&s_acc[wid][3][4 * lane] = a3;
    if (lane == 0) { s_lred[wid][0] = l0; s_lred[wid][1] = l1; s_lred[wid][2] = l2; s_lred[wid][3] = l3; }
    __syncthreads();

    // ---- cross-warp reduce + write partials ----
    for (int idx = threadIdx.x; idx < GG * DH; idx += 256) {
        int g = idx >> 7, d = idx & 127;
        float s = 0.f;
        #pragma unroll
        for (int w = 0; w < 8; w++) s += s_acc[w][g][d];
        g_pacc[(((size_t)bkv * NCHUNK + chunk) * GG + g) * DH + d] = s;
    }
    if (threadIdx.x < GG) {
        int g = threadIdx.x;
        float mm = -1e30f, L = 0.f;
        #pragma unroll
        for (int w = 0; w < 8; w++) { mm = fmaxf(mm, s_red[w][g]); L += s_lred[w][g]; }
        size_t base = (((size_t)bkv * NCHUNK + chunk) * GG + g) * 2;
        g_pml[base] = mm;
        g_pml[base + 1] = L;
    }
}

// ---------------- combine split-KV partials ----------------
__global__ void combine_kernel(const int* __restrict__ sp_ptr)
{
    const int h = blockIdx.x, b = blockIdx.y, d = threadIdx.x;
    const int sp = *sp_ptr;
    const int nact = sp / CHUNK + 1;
    const int kvh = h >> 2, g = h & 3;
    const int bkv = b * HKV + kvh;

    float M = -1e30f;
    for (int c = 0; c < nact; c++)
        M = fmaxf(M, g_pml[(((size_t)bkv * NCHUNK + c) * GG + g) * 2]);

    float L = 0.f, acc = 0.f;
    for (int c = 0; c < nact; c++) {
        size_t mlb = (((size_t)bkv * NCHUNK + c) * GG + g) * 2;
        float f = __expf(g_pml[mlb] - M);
        L += g_pml[mlb + 1] * f;
        acc += g_pacc[(((size_t)bkv * NCHUNK + c) * GG + g) * DH + d] * f;
    }
    g_attn[(size_t)(b * HH + h) * DH + d] = acc / L;
}

// ---------------- launcher ----------------
extern "C" void kernel_launch(void* const* d_in, const int* in_sizes, int n_in,
                              void* d_out, int out_size)
{
    const float* x   = (const float*)d_in[0];
    const float* wq  = (const float*)d_in[1];
    const float* wk  = (const float*)d_in[2];
    const float* wv  = (const float*)d_in[3];
    const float* wo  = (const float*)d_in[4];
    const float* rot = (const float*)d_in[5];
    // d_in[6] = attn_mask: not read (semantics derived from start_pos)
    const float* kc  = (const float*)d_in[7];
    const float* vc  = (const float*)d_in[8];
    const int*   sp  = (const int*)d_in[9];
    float* out = (float*)d_out;

    // rot_mat may be (1,B,DH,DH) materialized or a single (DH,DH); pick stride safely
    int rot_b_stride = (in_sizes[5] >= BB * DH * DH) ? DH * DH : 0;

    proj_qkv_kernel<<<dim3(EQKV / 512, SPLITS), 256>>>(x, wq, wk, wv);
    reduce_qkv_kernel<<<(BB * EQKV + 255) / 256, 256>>>();
    rotate_kernel<<<dim3(HH + HKV, BB), DH>>>(rot, rot_b_stride);
    attn_kernel<<<dim3(NCHUNK, HKV, BB), 256>>>(kc, vc, sp);
    combine_kernel<<<dim3(HH, BB), DH>>>(sp);
    proj_o_kernel<<<dim3(DD / 512, SPLITS), 256>>>(wo);
    reduce_o_kernel<<<(BB * DD + 255) / 256, 256>>>(out);
}